// round 6
// baseline (speedup 1.0000x reference)
#include <cuda_runtime.h>
#include <cuda_bf16.h>
#include <math.h>
#include <stdint.h>

#define B   64
#define T   2048
#define DL  1024
#define DE  512
#define DA  128
#define NF  32
#define KW  31
#define PADW 15
#define KC  (DE + NF)      // 544
#define CK  16             // K per chunk (one m16n8k16 step)
#define NCH (KC / CK)      // 34 chunks, exact

// dynamic smem stage layout (bytes)
#define A_STRIDE_W 12                  // words per A row (8 data + 4 pad) -> conflict-free
#define A_PLANE    (128 * A_STRIDE_W * 4)   // 6144
#define B_FRAG_BYTES 8192              // 16 nt * 32 lanes * 4 u32
#define STAGE (2 * A_PLANE + B_FRAG_BYTES)  // 20480
#define NSTAGE 3
#define DSM_BYTES (NSTAGE * STAGE)     // 61440 (opt-in)

// ---------------- scratch (static device memory; no allocations) -------------
__device__ __align__(16) float g_qq[B][DA];           // query proj + bq + bm
__device__ __align__(16) float g_conv[B][T][NF];      // location conv output
__device__ __align__(16) float g_e[B][T];             // energies
__device__ __align__(16) uint4 g_Bfrag[NCH * 16 * 32];  // Wcat bf16 hi/lo fragments

// ---------------- helpers ----------------------------------------------------
__device__ __forceinline__ unsigned smem_u32(const void* p) {
    return (unsigned)__cvta_generic_to_shared(p);
}
__device__ __forceinline__ void cpasync16(void* smem, const void* gmem) {
    asm volatile("cp.async.cg.shared.global [%0], [%1], 16;\n"
                 :: "r"(smem_u32(smem)), "l"(gmem));
}
__device__ __forceinline__ void mma_bf16(float* c, const unsigned* a, unsigned b0, unsigned b1) {
    asm volatile(
        "mma.sync.aligned.m16n8k16.row.col.f32.bf16.bf16.f32 "
        "{%0,%1,%2,%3}, {%4,%5,%6,%7}, {%8,%9}, {%0,%1,%2,%3};\n"
        : "+f"(c[0]), "+f"(c[1]), "+f"(c[2]), "+f"(c[3])
        : "r"(a[0]), "r"(a[1]), "r"(a[2]), "r"(a[3]), "r"(b0), "r"(b1));
}
__device__ __forceinline__ unsigned pack_hi_lo(float a0, float a1, unsigned& lo_out) {
    __nv_bfloat16 h0 = __float2bfloat16(a0);
    __nv_bfloat16 h1 = __float2bfloat16(a1);
    __nv_bfloat16 l0 = __float2bfloat16(a0 - __bfloat162float(h0));
    __nv_bfloat16 l1 = __float2bfloat16(a1 - __bfloat162float(h1));
    __nv_bfloat162 hh = __halves2bfloat162(h0, h1);
    __nv_bfloat162 ll = __halves2bfloat162(l0, l1);
    lo_out = *reinterpret_cast<unsigned*>(&ll);
    return *reinterpret_cast<unsigned*>(&hh);
}

// ---------------- K0a: qq[b][a] = query[b]·Wq[a] + bq[a] + bm[a] --------------
__global__ void k_qq(const float* __restrict__ query, const float* __restrict__ Wq,
                     const float* __restrict__ bq, const float* __restrict__ bm) {
    __shared__ float4 sq[DL / 4];
    int b = blockIdx.x, tid = threadIdx.x;
    for (int i = tid; i < DL / 4; i += 128)
        sq[i] = ((const float4*)(query + (size_t)b * DL))[i];
    __syncthreads();
    int w = tid >> 5, lane = tid & 31;
    int a0 = blockIdx.y * 32 + w * 8;
    #pragma unroll
    for (int j = 0; j < 8; j++) {
        int a = a0 + j;
        const float4* wr = (const float4*)(Wq + (size_t)a * DL);
        float s = 0.f;
        #pragma unroll
        for (int k = 0; k < DL / 128; k++) {
            float4 q4 = sq[lane + 32 * k];
            float4 w4 = wr[lane + 32 * k];
            s += q4.x * w4.x + q4.y * w4.y + q4.z * w4.z + q4.w * w4.w;
        }
        #pragma unroll
        for (int o = 16; o; o >>= 1) s += __shfl_xor_sync(0xffffffffu, s, o);
        if (lane == 0) g_qq[b][a] = s + bq[a] + bm[a];
    }
}

// ---------------- K0b: Wcat -> bf16 hi/lo mma fragments ----------------------
__global__ void k_prepB(const float* __restrict__ Wm, const float* __restrict__ Wloc) {
    int idx = blockIdx.x * 256 + threadIdx.x;        // one thread per (ch, nt, lane)
    if (idx >= NCH * 16 * 32) return;
    int lane = idx & 31, nt = (idx >> 5) & 15, ch = idx >> 9;
    int g = lane >> 2, t = lane & 3;
    int n = nt * 8 + g;
    int k0 = ch * CK;
    float v[4];
    #pragma unroll
    for (int j = 0; j < 4; j++) {
        int k = k0 + ((j >> 1) ? (2 * t + 8) : (2 * t)) + (j & 1);
        v[j] = (k < DE) ? Wm[(size_t)n * DE + k] : Wloc[n * NF + (k - DE)];
    }
    unsigned lo0, lo1;
    unsigned hi0 = pack_hi_lo(v[0], v[1], lo0);
    unsigned hi1 = pack_hi_lo(v[2], v[3], lo1);
    g_Bfrag[idx] = make_uint4(hi0, hi1, lo0, lo1);
}

// ---------------- K2: location conv (same padding), [B][T][NF] ----------------
__global__ void k_conv(const float* __restrict__ aw, const float* __restrict__ Wconv) {
    __shared__ float s_aw[2][128 + KW - 1];
    __shared__ float s_w[NF * 2 * KW];
    int b = blockIdx.x, t0 = blockIdx.y * 128, tid = threadIdx.x;  // 128 threads
    for (int i = tid; i < NF * 2 * KW; i += 128) s_w[i] = Wconv[i];
    for (int c = 0; c < 2; c++)
        for (int i = tid; i < 128 + KW - 1; i += 128) {
            int t = t0 - PADW + i;
            s_aw[c][i] = (t >= 0 && t < T) ? aw[((size_t)b * 2 + c) * T + t] : 0.f;
        }
    __syncthreads();
    float out[NF];
    #pragma unroll 4
    for (int f = 0; f < NF; f++) {
        float acc = 0.f;
        #pragma unroll
        for (int c = 0; c < 2; c++)
            #pragma unroll
            for (int k = 0; k < KW; k++)
                acc += s_aw[c][tid + k] * s_w[(f * 2 + c) * KW + k];
        out[f] = acc;
    }
    float4* dst = (float4*)&g_conv[b][t0 + tid][0];
    #pragma unroll
    for (int j = 0; j < NF / 4; j++)
        dst[j] = make_float4(out[4 * j], out[4 * j + 1], out[4 * j + 2], out[4 * j + 3]);
}

// ---------------- K3: fused S=[mem|conv]·Wcat -> tanh -> e (bf16 3-term) -----
// CTA = one (b, 128-t tile): 128x128x544 GEMM. 512 threads, 4Mx4N warps.
// 3-stage pipeline, prefetch distance 2: LDG/cp.async latency fully covered.
__global__ __launch_bounds__(512) void k_main(const float* __restrict__ mem,
                                              const float* __restrict__ Wv,
                                              const float* __restrict__ bv) {
    extern __shared__ __align__(16) char dsm[];
    __shared__ float s_qq[DA], s_wv[DA], s_esum[128];

    int tid = threadIdx.x, lane = tid & 31, w = tid >> 5;
    int g = lane >> 2, t4 = lane & 3;
    int wM = w & 3, wN = w >> 2;                     // 4 x 4 warps
    int t0 = blockIdx.x * 128, b = blockIdx.y;

    if (tid < DA) { s_qq[tid] = g_qq[b][tid]; s_wv[tid] = Wv[tid]; }
    if (tid >= 128 && tid < 256) s_esum[tid - 128] = 0.f;

    const float* memB = mem + ((size_t)b * T + t0) * DE;
    int arow = tid >> 2, aq = tid & 3;               // this thread's A slot (1 float4)

    float acc[2][4][4];
    #pragma unroll
    for (int mt = 0; mt < 2; mt++)
        #pragma unroll
        for (int nt = 0; nt < 4; nt++)
            #pragma unroll
            for (int j = 0; j < 4; j++) acc[mt][nt][j] = 0.f;

    // ---- helpers ----
    auto ldA = [&](int ch, float4& v) {
        int kk0 = ch * CK + aq * 4;
        v = (kk0 < DE)
            ? *(const float4*)(memB + (size_t)arow * DE + kk0)
            : *(const float4*)(&g_conv[b][t0 + arow][kk0 - DE]);
    };
    auto stA = [&](int buf, float4 v) {
        char* st = dsm + buf * STAGE;
        unsigned lo0, lo1;
        unsigned hi0 = pack_hi_lo(v.x, v.y, lo0);
        unsigned hi1 = pack_hi_lo(v.z, v.w, lo1);
        unsigned boff = (arow * A_STRIDE_W + aq * 2) * 4;
        *(uint2*)(st + boff)           = make_uint2(hi0, hi1);
        *(uint2*)(st + A_PLANE + boff) = make_uint2(lo0, lo1);
    };
    auto ldB = [&](int ch, int buf) {
        char* bb = dsm + buf * STAGE + 2 * A_PLANE;
        const char* src = (const char*)&g_Bfrag[ch * 512];
        cpasync16(bb + tid * 16, src + tid * 16);
        asm volatile("cp.async.commit_group;\n");
    };

    // ---- prologue: fill stages 0 and 1 ----
    {
        float4 v0, v1;
        ldA(0, v0);
        ldA(1, v1);
        ldB(0, 0);          // group for ch=0
        ldB(1, 1);          // group for ch=1
        stA(0, v0);
        stA(1, v1);
        asm volatile("cp.async.wait_group 0;\n");
    }
    __syncthreads();

    // ---- main loop: at iter ch, stage ch%3 is ready; prefetch ch+2 ----
    int cur = 0;
    for (int ch = 0; ch < NCH; ch++) {
        bool pre = (ch + 2) < NCH;
        int nxt = cur + 2; if (nxt >= NSTAGE) nxt -= NSTAGE;  // (ch+2)%3
        float4 v;
        if (pre) { ldA(ch + 2, v); ldB(ch + 2, nxt); }

        const char* st = dsm + cur * STAGE;
        const unsigned* Ahi = (const unsigned*)st;
        const unsigned* Alo = (const unsigned*)(st + A_PLANE);
        const uint4*    Bf  = (const uint4*)(st + 2 * A_PLANE);

        unsigned ahi[2][4], alo[2][4];
        #pragma unroll
        for (int mt = 0; mt < 2; mt++) {
            int r0 = (wM * 32 + mt * 16 + g) * A_STRIDE_W;
            int r8 = r0 + 8 * A_STRIDE_W;
            ahi[mt][0] = Ahi[r0 + t4];     ahi[mt][1] = Ahi[r8 + t4];
            ahi[mt][2] = Ahi[r0 + t4 + 4]; ahi[mt][3] = Ahi[r8 + t4 + 4];
            alo[mt][0] = Alo[r0 + t4];     alo[mt][1] = Alo[r8 + t4];
            alo[mt][2] = Alo[r0 + t4 + 4]; alo[mt][3] = Alo[r8 + t4 + 4];
        }
        #pragma unroll
        for (int nt = 0; nt < 4; nt++) {
            uint4 bf = Bf[(wN * 4 + nt) * 32 + lane];
            #pragma unroll
            for (int mt = 0; mt < 2; mt++) {
                mma_bf16(acc[mt][nt], ahi[mt], bf.x, bf.y);   // hi*hi
                mma_bf16(acc[mt][nt], alo[mt], bf.x, bf.y);   // lo*hi
                mma_bf16(acc[mt][nt], ahi[mt], bf.z, bf.w);   // hi*lo
            }
        }

        if (pre) {
            stA(nxt, v);
            asm volatile("cp.async.wait_group 1;\n");   // newest group may float
        } else {
            asm volatile("cp.async.wait_group 0;\n");
        }
        __syncthreads();
        cur = cur + 1 == NSTAGE ? 0 : cur + 1;
    }

    // ---- epilogue: e[t] = bv + sum_a Wv[a]*tanh(acc + qq[a]) ----
    #pragma unroll
    for (int mt = 0; mt < 2; mt++) {
        #pragma unroll
        for (int half = 0; half < 2; half++) {
            int rloc = wM * 32 + mt * 16 + g + 8 * half;
            float p = 0.f;
            #pragma unroll
            for (int nt = 0; nt < 4; nt++) {
                int c0 = wN * 32 + nt * 8 + 2 * t4;
                float x0 = acc[mt][nt][2 * half + 0] + s_qq[c0];
                float x1 = acc[mt][nt][2 * half + 1] + s_qq[c0 + 1];
                float e0 = __expf(2.f * x0), e1 = __expf(2.f * x1);
                p += s_wv[c0]     * (1.f - __fdividef(2.f, e0 + 1.f));
                p += s_wv[c0 + 1] * (1.f - __fdividef(2.f, e1 + 1.f));
            }
            p += __shfl_xor_sync(0xffffffffu, p, 1);
            p += __shfl_xor_sync(0xffffffffu, p, 2);
            if (t4 == 0) atomicAdd(&s_esum[rloc], p);
        }
    }
    __syncthreads();
    if (tid < 128) g_e[b][t0 + tid] = s_esum[tid] + bv[0];
}

// ---------------- K4: per-b softmax -> weights to d_out; zero ctx ------------
__global__ void k_soft(float* __restrict__ out_w, float* __restrict__ out_ctx) {
    __shared__ float red[256];
    int b = blockIdx.x, tid = threadIdx.x;            // 256 threads
    out_ctx[(size_t)b * DE + tid] = 0.f;
    out_ctx[(size_t)b * DE + tid + 256] = 0.f;

    float v[8];
    float m = -1e30f;
    #pragma unroll
    for (int j = 0; j < 8; j++) { v[j] = g_e[b][tid + 256 * j]; m = fmaxf(m, v[j]); }
    red[tid] = m; __syncthreads();
    for (int s = 128; s; s >>= 1) { if (tid < s) red[tid] = fmaxf(red[tid], red[tid + s]); __syncthreads(); }
    m = red[0]; __syncthreads();
    float sum = 0.f;
    #pragma unroll
    for (int j = 0; j < 8; j++) { v[j] = expf(v[j] - m); sum += v[j]; }
    red[tid] = sum; __syncthreads();
    for (int s = 128; s; s >>= 1) { if (tid < s) red[tid] += red[tid + s]; __syncthreads(); }
    float inv = 1.f / red[0];
    #pragma unroll
    for (int j = 0; j < 8; j++) out_w[(size_t)b * T + tid + 256 * j] = v[j] * inv;
}

// ---------------- K5: context[b][d] += sum_t w[t]*mem[b][t][d] ---------------
__global__ void k_ctx(const float* __restrict__ mem, const float* __restrict__ w,
                      float* __restrict__ ctx) {
    __shared__ float sw[256];
    int b = blockIdx.x, dc = blockIdx.y, ts = blockIdx.z;
    int tid = threadIdx.x;                            // 128 threads
    int t0 = ts * 256;
    for (int i = tid; i < 256; i += 128) sw[i] = w[(size_t)b * T + t0 + i];
    __syncthreads();
    int d = dc * 128 + tid;
    const float* mp = mem + ((size_t)b * T + t0) * DE + d;
    float acc = 0.f;
    #pragma unroll 16
    for (int i = 0; i < 256; i++) acc += sw[i] * mp[(size_t)i * DE];
    atomicAdd(&ctx[(size_t)b * DE + d], acc);
}

// ---------------- launch ------------------------------------------------------
extern "C" void kernel_launch(void* const* d_in, const int* in_sizes, int n_in,
                              void* d_out, int out_size) {
    const float* query  = (const float*)d_in[0];
    const float* memory = (const float*)d_in[1];
    const float* aw     = (const float*)d_in[2];
    const float* Wq     = (const float*)d_in[3];
    const float* bq     = (const float*)d_in[4];
    const float* Wm     = (const float*)d_in[5];
    const float* bm     = (const float*)d_in[6];
    const float* Wconv  = (const float*)d_in[7];
    const float* Wloc   = (const float*)d_in[8];
    const float* Wv     = (const float*)d_in[9];
    const float* bv     = (const float*)d_in[10];

    float* out_ctx = (float*)d_out;            // [B][DE]
    float* out_w   = (float*)d_out + B * DE;   // [B][T]

    static int smem_set = 0;
    if (!smem_set) {
        cudaFuncSetAttribute(k_main, cudaFuncAttributeMaxDynamicSharedMemorySize, DSM_BYTES);
        smem_set = 1;
    }

    k_qq   <<<dim3(B, 4), 128>>>(query, Wq, bq, bm);
    k_prepB<<<(NCH * 16 * 32 + 255) / 256, 256>>>(Wm, Wloc);
    k_conv <<<dim3(B, T / 128), 128>>>(aw, Wconv);
    k_main <<<dim3(T / 128, B), 512, DSM_BYTES>>>(memory, Wv, bv);
    k_soft <<<B, 256>>>(out_w, out_ctx);
    k_ctx  <<<dim3(B, DE / 128, T / 256), 128>>>(memory, out_w, out_ctx);
}

// round 7
// speedup vs baseline: 1.5145x; 1.5145x over previous
#include <cuda_runtime.h>
#include <cuda_fp16.h>
#include <math.h>
#include <stdint.h>

#define B   64
#define T   2048
#define DL  1024
#define DE  512
#define DA  128
#define NF  32
#define KW  31
#define PADW 15
#define KC  (DE + NF)      // 544
#define CK  32             // K per chunk (two m16n8k16 k-steps)
#define NCH (KC / CK)      // 17 chunks, exact

// dynamic smem stage layout (bytes)
#define A_STRIDE_W 20                  // words per A row (16 data + 4 pad) -> conflict-free
#define A_PLANE    (128 * A_STRIDE_W * 4)   // 10240
#define B_FRAG_BYTES (2 * 16 * 32 * 8) // 2 ksteps * 16 nt * 32 lanes * uint2 = 8192
#define STAGE (A_PLANE + B_FRAG_BYTES) // 18432
#define NSTAGE 3
#define DSM_BYTES (NSTAGE * STAGE)     // 55296 (opt-in)

// ---------------- scratch (static device memory; no allocations) -------------
__device__ __align__(16) float g_qq[B][DA];           // query proj + bq + bm
__device__ __align__(16) float g_conv[B][T][NF];      // location conv output
__device__ __align__(16) float g_e[B][T];             // energies
__device__ __align__(16) uint2 g_Bfrag[NCH * 2 * 16 * 32];  // Wcat fp16 fragments
__device__ __align__(16) float g_pctx[B * 16 * DE];   // per-tile partial contexts
__device__ __align__(16) float2 g_ms[B * 16];         // per-tile (max, sumexp)

// ---------------- helpers ----------------------------------------------------
__device__ __forceinline__ unsigned smem_u32(const void* p) {
    return (unsigned)__cvta_generic_to_shared(p);
}
__device__ __forceinline__ void cpasync16(void* smem, const void* gmem) {
    asm volatile("cp.async.cg.shared.global [%0], [%1], 16;\n"
                 :: "r"(smem_u32(smem)), "l"(gmem));
}
__device__ __forceinline__ void mma_f16(float* c, const unsigned* a, unsigned b0, unsigned b1) {
    asm volatile(
        "mma.sync.aligned.m16n8k16.row.col.f32.f16.f16.f32 "
        "{%0,%1,%2,%3}, {%4,%5,%6,%7}, {%8,%9}, {%0,%1,%2,%3};\n"
        : "+f"(c[0]), "+f"(c[1]), "+f"(c[2]), "+f"(c[3])
        : "r"(a[0]), "r"(a[1]), "r"(a[2]), "r"(a[3]), "r"(b0), "r"(b1));
}
__device__ __forceinline__ unsigned pack_h2(float a0, float a1) {
    __half2 h = __floats2half2_rn(a0, a1);
    return *reinterpret_cast<unsigned*>(&h);
}

// ---------------- K0a: qq[b][a] = query[b]·Wq[a] + bq[a] + bm[a] --------------
__global__ void k_qq(const float* __restrict__ query, const float* __restrict__ Wq,
                     const float* __restrict__ bq, const float* __restrict__ bm) {
    __shared__ float4 sq[DL / 4];
    int b = blockIdx.x, tid = threadIdx.x;
    for (int i = tid; i < DL / 4; i += 128)
        sq[i] = ((const float4*)(query + (size_t)b * DL))[i];
    __syncthreads();
    int w = tid >> 5, lane = tid & 31;
    int a0 = blockIdx.y * 32 + w * 8;
    #pragma unroll
    for (int j = 0; j < 8; j++) {
        int a = a0 + j;
        const float4* wr = (const float4*)(Wq + (size_t)a * DL);
        float s = 0.f;
        #pragma unroll
        for (int k = 0; k < DL / 128; k++) {
            float4 q4 = sq[lane + 32 * k];
            float4 w4 = wr[lane + 32 * k];
            s += q4.x * w4.x + q4.y * w4.y + q4.z * w4.z + q4.w * w4.w;
        }
        #pragma unroll
        for (int o = 16; o; o >>= 1) s += __shfl_xor_sync(0xffffffffu, s, o);
        if (lane == 0) g_qq[b][a] = s + bq[a] + bm[a];
    }
}

// ---------------- K0b: Wcat -> fp16 mma fragments ----------------------------
// For m16n8k16 row.col: lane l (g=l>>2, t=l&3), col n = nt*8+g (within window s):
// b0 = {B[2t][n], B[2t+1][n]}, b1 = {B[2t+8][n], B[2t+9][n]}.
__global__ void k_prepB(const float* __restrict__ Wm, const float* __restrict__ Wloc) {
    int idx = blockIdx.x * 256 + threadIdx.x;        // one per (ch, s, nt, lane)
    if (idx >= NCH * 2 * 16 * 32) return;
    int lane = idx & 31, nt = (idx >> 5) & 15, s = (idx >> 9) & 1, ch = idx >> 10;
    int g = lane >> 2, t = lane & 3;
    int n = nt * 8 + g;
    int k0 = ch * CK + s * 16;
    float v[4];
    #pragma unroll
    for (int j = 0; j < 4; j++) {
        int k = k0 + ((j >> 1) ? (2 * t + 8) : (2 * t)) + (j & 1);
        v[j] = (k < DE) ? Wm[(size_t)n * DE + k] : Wloc[n * NF + (k - DE)];
    }
    g_Bfrag[idx] = make_uint2(pack_h2(v[0], v[1]), pack_h2(v[2], v[3]));
}

// ---------------- K2: location conv (same padding), [B][T][NF] ----------------
__global__ void k_conv(const float* __restrict__ aw, const float* __restrict__ Wconv) {
    __shared__ float s_aw[2][128 + KW - 1];
    __shared__ float s_w[NF * 2 * KW];
    int b = blockIdx.x, t0 = blockIdx.y * 128, tid = threadIdx.x;  // 128 threads
    for (int i = tid; i < NF * 2 * KW; i += 128) s_w[i] = Wconv[i];
    for (int c = 0; c < 2; c++)
        for (int i = tid; i < 128 + KW - 1; i += 128) {
            int t = t0 - PADW + i;
            s_aw[c][i] = (t >= 0 && t < T) ? aw[((size_t)b * 2 + c) * T + t] : 0.f;
        }
    __syncthreads();
    float out[NF];
    #pragma unroll 4
    for (int f = 0; f < NF; f++) {
        float acc = 0.f;
        #pragma unroll
        for (int c = 0; c < 2; c++)
            #pragma unroll
            for (int k = 0; k < KW; k++)
                acc += s_aw[c][tid + k] * s_w[(f * 2 + c) * KW + k];
        out[f] = acc;
    }
    float4* dst = (float4*)&g_conv[b][t0 + tid][0];
    #pragma unroll
    for (int j = 0; j < NF / 4; j++)
        dst[j] = make_float4(out[4 * j], out[4 * j + 1], out[4 * j + 2], out[4 * j + 3]);
}

// ---------------- K3: fused S=[mem|conv]·Wcat -> tanh -> e -> flash partial ---
// CTA = one (b, 128-t tile): 128x128x544 fp16 GEMM (1-term), then per-tile
// softmax partials + partial context GEMV (memory tile re-read from L2).
__global__ __launch_bounds__(512) void k_main(const float* __restrict__ mem,
                                              const float* __restrict__ Wv,
                                              const float* __restrict__ bv) {
    extern __shared__ __align__(16) char dsm[];
    __shared__ float s_qq[DA], s_wv[DA], s_esum[128], sp[128];
    __shared__ float s_ml;

    int tid = threadIdx.x, lane = tid & 31, w = tid >> 5;
    int g = lane >> 2, t4 = lane & 3;
    int wM = w & 3, wN = w >> 2;                     // 4 x 4 warps
    int tx = blockIdx.x, b = blockIdx.y;
    int t0 = tx * 128;

    if (tid < DA) { s_qq[tid] = g_qq[b][tid]; s_wv[tid] = Wv[tid]; }
    if (tid >= 128 && tid < 256) s_esum[tid - 128] = 0.f;

    const float* memB = mem + ((size_t)b * T + t0) * DE;
    int arow = tid >> 2, aq = tid & 3;               // A slot: 8 cols per thread

    float acc[2][4][4];
    #pragma unroll
    for (int mt = 0; mt < 2; mt++)
        #pragma unroll
        for (int nt = 0; nt < 4; nt++)
            #pragma unroll
            for (int j = 0; j < 4; j++) acc[mt][nt][j] = 0.f;

    // ---- helpers ----
    auto ldA = [&](int ch, float4* v) {
        int kk0 = ch * CK + aq * 8;
        const float4* src = (kk0 < DE)
            ? (const float4*)(memB + (size_t)arow * DE + kk0)
            : (const float4*)(&g_conv[b][t0 + arow][kk0 - DE]);
        v[0] = src[0]; v[1] = src[1];
    };
    auto stA = [&](int buf, const float4* v) {
        unsigned* st = (unsigned*)(dsm + buf * STAGE);
        unsigned h0 = pack_h2(v[0].x, v[0].y), h1 = pack_h2(v[0].z, v[0].w);
        unsigned h2 = pack_h2(v[1].x, v[1].y), h3 = pack_h2(v[1].z, v[1].w);
        *(uint4*)(st + arow * A_STRIDE_W + aq * 4) = make_uint4(h0, h1, h2, h3);
    };
    auto ldB = [&](int ch, int buf) {
        char* bb = dsm + buf * STAGE + A_PLANE;
        const char* src = (const char*)&g_Bfrag[ch * 1024];
        cpasync16(bb + tid * 16, src + tid * 16);
        asm volatile("cp.async.commit_group;\n");
    };

    // ---- prologue: fill stages 0 and 1 ----
    {
        float4 v0[2], v1[2];
        ldA(0, v0);
        ldA(1, v1);
        ldB(0, 0);
        ldB(1, 1);
        stA(0, v0);
        stA(1, v1);
        asm volatile("cp.async.wait_group 0;\n");
    }
    __syncthreads();

    // ---- main loop: stage cur ready; prefetch ch+2 into (cur+2)%3 ----
    int cur = 0;
    for (int ch = 0; ch < NCH; ch++) {
        bool pre = (ch + 2) < NCH;
        int nxt = cur + 2; if (nxt >= NSTAGE) nxt -= NSTAGE;
        float4 v[2];
        if (pre) { ldA(ch + 2, v); ldB(ch + 2, nxt); }

        const unsigned* As = (const unsigned*)(dsm + cur * STAGE);
        const uint2*    Bf = (const uint2*)(dsm + cur * STAGE + A_PLANE);

        #pragma unroll
        for (int s = 0; s < 2; s++) {
            unsigned af[2][4];
            #pragma unroll
            for (int mt = 0; mt < 2; mt++) {
                int r0 = (wM * 32 + mt * 16 + g) * A_STRIDE_W + s * 8 + t4;
                int r8 = r0 + 8 * A_STRIDE_W;
                af[mt][0] = As[r0];     af[mt][1] = As[r8];
                af[mt][2] = As[r0 + 4]; af[mt][3] = As[r8 + 4];
            }
            #pragma unroll
            for (int nt = 0; nt < 4; nt++) {
                uint2 bf = Bf[(s * 16 + wN * 4 + nt) * 32 + lane];
                #pragma unroll
                for (int mt = 0; mt < 2; mt++)
                    mma_f16(acc[mt][nt], af[mt], bf.x, bf.y);
            }
        }

        if (pre) {
            stA(nxt, v);
            asm volatile("cp.async.wait_group 1;\n");
        } else {
            asm volatile("cp.async.wait_group 0;\n");
        }
        __syncthreads();
        cur = cur + 1 == NSTAGE ? 0 : cur + 1;
    }

    // ---- e[t] = bv + sum_a Wv[a]*tanh(acc + qq[a]) ----
    #pragma unroll
    for (int mt = 0; mt < 2; mt++) {
        #pragma unroll
        for (int half = 0; half < 2; half++) {
            int rloc = wM * 32 + mt * 16 + g + 8 * half;
            float p = 0.f;
            #pragma unroll
            for (int nt = 0; nt < 4; nt++) {
                int c0 = wN * 32 + nt * 8 + 2 * t4;
                float x0 = acc[mt][nt][2 * half + 0] + s_qq[c0];
                float x1 = acc[mt][nt][2 * half + 1] + s_qq[c0 + 1];
                float e0 = __expf(2.f * x0), e1 = __expf(2.f * x1);
                p += s_wv[c0]     * (1.f - __fdividef(2.f, e0 + 1.f));
                p += s_wv[c0 + 1] * (1.f - __fdividef(2.f, e1 + 1.f));
            }
            p += __shfl_xor_sync(0xffffffffu, p, 1);
            p += __shfl_xor_sync(0xffffffffu, p, 2);
            if (t4 == 0) atomicAdd(&s_esum[rloc], p);
        }
    }
    __syncthreads();

    // ---- flash partials: m_l, p_t, s_l, partial ctx ----
    if (tid < 32) {
        float m = fmaxf(fmaxf(s_esum[tid], s_esum[tid + 32]),
                        fmaxf(s_esum[tid + 64], s_esum[tid + 96]));
        #pragma unroll
        for (int o = 16; o; o >>= 1) m = fmaxf(m, __shfl_xor_sync(0xffffffffu, m, o));
        if (tid == 0) s_ml = m;
    }
    if (tid < 128) g_e[b][t0 + tid] = s_esum[tid] + bv[0];
    __syncthreads();
    if (tid < 128) sp[tid] = __expf(s_esum[tid] - s_ml);
    __syncthreads();
    if (tid < 32) {
        float ssum = sp[tid] + sp[tid + 32] + sp[tid + 64] + sp[tid + 96];
        #pragma unroll
        for (int o = 16; o; o >>= 1) ssum += __shfl_xor_sync(0xffffffffu, ssum, o);
        if (tid == 0) g_ms[b * 16 + tx] = make_float2(s_ml, ssum);
    }
    // partial context: pctx[d] = sum_t sp[t] * mem[t][d]  (tile is L2-hot)
    {
        const float* mp = memB + tid;
        float c = 0.f;
        #pragma unroll 16
        for (int t = 0; t < 128; t++) c += sp[t] * mp[(size_t)t * DE];
        g_pctx[((size_t)b * 16 + tx) * DE + tid] = c;
    }
}

// ---------------- K4: per-b softmax -> weights to d_out ----------------------
__global__ void k_soft(float* __restrict__ out_w) {
    __shared__ float red[256];
    int b = blockIdx.x, tid = threadIdx.x;            // 256 threads
    float v[8];
    float m = -1e30f;
    #pragma unroll
    for (int j = 0; j < 8; j++) { v[j] = g_e[b][tid + 256 * j]; m = fmaxf(m, v[j]); }
    red[tid] = m; __syncthreads();
    for (int s = 128; s; s >>= 1) { if (tid < s) red[tid] = fmaxf(red[tid], red[tid + s]); __syncthreads(); }
    m = red[0]; __syncthreads();
    float sum = 0.f;
    #pragma unroll
    for (int j = 0; j < 8; j++) { v[j] = expf(v[j] - m); sum += v[j]; }
    red[tid] = sum; __syncthreads();
    for (int s = 128; s; s >>= 1) { if (tid < s) red[tid] += red[tid + s]; __syncthreads(); }
    float inv = 1.f / red[0];
    #pragma unroll
    for (int j = 0; j < 8; j++) out_w[(size_t)b * T + tid + 256 * j] = v[j] * inv;
}

// ---------------- K5: combine partial contexts -------------------------------
__global__ void k_comb(float* __restrict__ out_ctx) {
    __shared__ float sm[16], ss[16];
    int b = blockIdx.x, tid = threadIdx.x;            // 512 threads
    if (tid < 16) {
        float2 v = g_ms[b * 16 + tid];
        sm[tid] = v.x; ss[tid] = v.y;
    }
    __syncthreads();
    float mg = -1e30f;
    #pragma unroll
    for (int l = 0; l < 16; l++) mg = fmaxf(mg, sm[l]);
    float Sg = 0.f;
    float sc[16];
    #pragma unroll
    for (int l = 0; l < 16; l++) { sc[l] = expf(sm[l] - mg); Sg += ss[l] * sc[l]; }
    float invS = 1.f / Sg;
    float acc = 0.f;
    #pragma unroll
    for (int l = 0; l < 16; l++)
        acc += sc[l] * g_pctx[((size_t)b * 16 + l) * DE + tid];
    out_ctx[(size_t)b * DE + tid] = acc * invS;
}

// ---------------- launch ------------------------------------------------------
extern "C" void kernel_launch(void* const* d_in, const int* in_sizes, int n_in,
                              void* d_out, int out_size) {
    const float* query  = (const float*)d_in[0];
    const float* memory = (const float*)d_in[1];
    const float* aw     = (const float*)d_in[2];
    const float* Wq     = (const float*)d_in[3];
    const float* bq     = (const float*)d_in[4];
    const float* Wm     = (const float*)d_in[5];
    const float* bm     = (const float*)d_in[6];
    const float* Wconv  = (const float*)d_in[7];
    const float* Wloc   = (const float*)d_in[8];
    const float* Wv     = (const float*)d_in[9];
    const float* bv     = (const float*)d_in[10];

    float* out_ctx = (float*)d_out;            // [B][DE]
    float* out_w   = (float*)d_out + B * DE;   // [B][T]

    static int smem_set = 0;
    if (!smem_set) {
        cudaFuncSetAttribute(k_main, cudaFuncAttributeMaxDynamicSharedMemorySize, DSM_BYTES);
        smem_set = 1;
    }

    k_qq   <<<dim3(B, 4), 128>>>(query, Wq, bq, bm);
    k_prepB<<<(NCH * 2 * 16 * 32 + 255) / 256, 256>>>(Wm, Wloc);
    k_conv <<<dim3(B, T / 128), 128>>>(aw, Wconv);
    k_main <<<dim3(T / 128, B), 512, DSM_BYTES>>>(memory, Wv, bv);
    k_soft <<<B, 256>>>(out_w);
    k_comb <<<B, 512>>>(out_ctx);
}

// round 8
// speedup vs baseline: 1.8584x; 1.2270x over previous
#include <cuda_runtime.h>
#include <cuda_fp16.h>
#include <math.h>
#include <stdint.h>

#define B   64
#define T   2048
#define DL  1024
#define DE  512
#define DA  128
#define NF  32
#define KW  31
#define PADW 15
#define KC  (DE + NF)      // 544
#define CK  32             // K per chunk (two m16n8k16 k-steps)
#define NCH (KC / CK)      // 17 chunks, exact
#define TM  64             // rows per CTA tile
#define NTILE (T / TM)     // 32 tiles per batch

// dynamic smem stage layout (bytes)
#define A_STRIDE_W 20                  // words per A row (16 data + 4 pad) -> conflict-free
#define A_PLANE    (TM * A_STRIDE_W * 4)    // 5120
#define B_FRAG_BYTES (2 * 16 * 32 * 8) // 8192
#define STAGE (A_PLANE + B_FRAG_BYTES) // 13312
#define NSTAGE 3
#define DSM_BYTES (NSTAGE * STAGE)     // 39936 (< 48KB default)

// ---------------- scratch (static device memory; no allocations) -------------
__device__ __align__(16) float g_qq[B][DA];           // query proj + bq + bm
__device__ __align__(16) float g_conv[B][T][NF];      // location conv output
__device__ __align__(16) float g_e[B][T];             // energies
__device__ __align__(16) uint2 g_Bfrag[NCH * 2 * 16 * 32];  // Wcat fp16 fragments
__device__ __align__(16) float g_pctx[B * NTILE * DE];  // per-tile partial contexts
__device__ __align__(16) float2 g_ms[B * NTILE];        // per-tile (max, sumexp)

// ---------------- helpers ----------------------------------------------------
__device__ __forceinline__ unsigned smem_u32(const void* p) {
    return (unsigned)__cvta_generic_to_shared(p);
}
__device__ __forceinline__ void cpasync16(void* smem, const void* gmem) {
    asm volatile("cp.async.cg.shared.global [%0], [%1], 16;\n"
                 :: "r"(smem_u32(smem)), "l"(gmem));
}
__device__ __forceinline__ void mma_f16(float* c, const unsigned* a, unsigned b0, unsigned b1) {
    asm volatile(
        "mma.sync.aligned.m16n8k16.row.col.f32.f16.f16.f32 "
        "{%0,%1,%2,%3}, {%4,%5,%6,%7}, {%8,%9}, {%0,%1,%2,%3};\n"
        : "+f"(c[0]), "+f"(c[1]), "+f"(c[2]), "+f"(c[3])
        : "r"(a[0]), "r"(a[1]), "r"(a[2]), "r"(a[3]), "r"(b0), "r"(b1));
}
__device__ __forceinline__ unsigned pack_h2(float a0, float a1) {
    __half2 h = __floats2half2_rn(a0, a1);
    return *reinterpret_cast<unsigned*>(&h);
}

// ---------------- K0a: qq[b][a] = query[b]·Wq[a] + bq[a] + bm[a] --------------
__global__ void k_qq(const float* __restrict__ query, const float* __restrict__ Wq,
                     const float* __restrict__ bq, const float* __restrict__ bm) {
    __shared__ float4 sq[DL / 4];
    int b = blockIdx.x, tid = threadIdx.x;
    for (int i = tid; i < DL / 4; i += 128)
        sq[i] = ((const float4*)(query + (size_t)b * DL))[i];
    __syncthreads();
    int w = tid >> 5, lane = tid & 31;
    int a0 = blockIdx.y * 32 + w * 8;
    #pragma unroll
    for (int j = 0; j < 8; j++) {
        int a = a0 + j;
        const float4* wr = (const float4*)(Wq + (size_t)a * DL);
        float s = 0.f;
        #pragma unroll
        for (int k = 0; k < DL / 128; k++) {
            float4 q4 = sq[lane + 32 * k];
            float4 w4 = wr[lane + 32 * k];
            s += q4.x * w4.x + q4.y * w4.y + q4.z * w4.z + q4.w * w4.w;
        }
        #pragma unroll
        for (int o = 16; o; o >>= 1) s += __shfl_xor_sync(0xffffffffu, s, o);
        if (lane == 0) g_qq[b][a] = s + bq[a] + bm[a];
    }
}

// ---------------- K0b: Wcat -> fp16 mma fragments ----------------------------
__global__ void k_prepB(const float* __restrict__ Wm, const float* __restrict__ Wloc) {
    int idx = blockIdx.x * 256 + threadIdx.x;        // one per (ch, s, nt, lane)
    if (idx >= NCH * 2 * 16 * 32) return;
    int lane = idx & 31, nt = (idx >> 5) & 15, s = (idx >> 9) & 1, ch = idx >> 10;
    int g = lane >> 2, t = lane & 3;
    int n = nt * 8 + g;
    int k0 = ch * CK + s * 16;
    float v[4];
    #pragma unroll
    for (int j = 0; j < 4; j++) {
        int k = k0 + ((j >> 1) ? (2 * t + 8) : (2 * t)) + (j & 1);
        v[j] = (k < DE) ? Wm[(size_t)n * DE + k] : Wloc[n * NF + (k - DE)];
    }
    g_Bfrag[idx] = make_uint2(pack_h2(v[0], v[1]), pack_h2(v[2], v[3]));
}

// ---------------- K2: location conv (same padding), [B][T][NF] ----------------
__global__ void k_conv(const float* __restrict__ aw, const float* __restrict__ Wconv) {
    __shared__ float s_aw[2][128 + KW - 1];
    __shared__ float s_w[NF * 2 * KW];
    int b = blockIdx.x, t0 = blockIdx.y * 128, tid = threadIdx.x;  // 128 threads
    for (int i = tid; i < NF * 2 * KW; i += 128) s_w[i] = Wconv[i];
    for (int c = 0; c < 2; c++)
        for (int i = tid; i < 128 + KW - 1; i += 128) {
            int t = t0 - PADW + i;
            s_aw[c][i] = (t >= 0 && t < T) ? aw[((size_t)b * 2 + c) * T + t] : 0.f;
        }
    __syncthreads();
    float out[NF];
    #pragma unroll 4
    for (int f = 0; f < NF; f++) {
        float acc = 0.f;
        #pragma unroll
        for (int c = 0; c < 2; c++)
            #pragma unroll
            for (int k = 0; k < KW; k++)
                acc += s_aw[c][tid + k] * s_w[(f * 2 + c) * KW + k];
        out[f] = acc;
    }
    float4* dst = (float4*)&g_conv[b][t0 + tid][0];
    #pragma unroll
    for (int j = 0; j < NF / 4; j++)
        dst[j] = make_float4(out[4 * j], out[4 * j + 1], out[4 * j + 2], out[4 * j + 3]);
}

// ---------------- K3: fused S=[mem|conv]·Wcat -> tanh -> e -> flash partial ---
// CTA = one (b, 64-t tile): 64x128x544 fp16 GEMM + per-tile softmax partials +
// partial context GEMV. 256 threads, 8 warps (2M x 4N), 3 CTAs/SM.
__global__ __launch_bounds__(256, 3) void k_main(const float* __restrict__ mem,
                                                 const float* __restrict__ Wv,
                                                 const float* __restrict__ bv) {
    extern __shared__ __align__(16) char dsm[];
    __shared__ float s_qq[DA], s_wv[DA], s_esum[TM], sp[TM];
    __shared__ float s_ml;

    int tid = threadIdx.x, lane = tid & 31, w = tid >> 5;
    int g = lane >> 2, t4 = lane & 3;
    int wM = w & 1, wN = w >> 1;                     // 2 x 4 warps
    int tx = blockIdx.x, b = blockIdx.y;
    int t0 = tx * TM;
    float bv0 = bv[0];

    if (tid < DA) { s_qq[tid] = g_qq[b][tid]; s_wv[tid] = Wv[tid]; }
    if (tid >= 128 && tid < 128 + TM) s_esum[tid - 128] = 0.f;

    const float* memB = mem + ((size_t)b * T + t0) * DE;
    int arow = tid >> 2, aq = tid & 3;               // A slot: 8 cols per thread

    float acc[2][4][4];
    #pragma unroll
    for (int mt = 0; mt < 2; mt++)
        #pragma unroll
        for (int nt = 0; nt < 4; nt++)
            #pragma unroll
            for (int j = 0; j < 4; j++) acc[mt][nt][j] = 0.f;

    // ---- helpers ----
    auto ldA = [&](int ch, float4* v) {
        int kk0 = ch * CK + aq * 8;
        const float4* src = (kk0 < DE)
            ? (const float4*)(memB + (size_t)arow * DE + kk0)
            : (const float4*)(&g_conv[b][t0 + arow][kk0 - DE]);
        v[0] = src[0]; v[1] = src[1];
    };
    auto stA = [&](int buf, const float4* v) {
        unsigned* st = (unsigned*)(dsm + buf * STAGE);
        unsigned h0 = pack_h2(v[0].x, v[0].y), h1 = pack_h2(v[0].z, v[0].w);
        unsigned h2 = pack_h2(v[1].x, v[1].y), h3 = pack_h2(v[1].z, v[1].w);
        *(uint4*)(st + arow * A_STRIDE_W + aq * 4) = make_uint4(h0, h1, h2, h3);
    };
    auto ldB = [&](int ch, int buf) {
        char* bb = dsm + buf * STAGE + A_PLANE;
        const char* src = (const char*)&g_Bfrag[ch * 1024];
        cpasync16(bb + tid * 16, src + tid * 16);
        cpasync16(bb + (tid + 256) * 16, src + (tid + 256) * 16);
        asm volatile("cp.async.commit_group;\n");
    };

    // ---- prologue: fill stages 0 and 1 ----
    {
        float4 v0[2], v1[2];
        ldA(0, v0);
        ldA(1, v1);
        ldB(0, 0);
        ldB(1, 1);
        stA(0, v0);
        stA(1, v1);
        asm volatile("cp.async.wait_group 0;\n");
    }
    __syncthreads();

    // ---- main loop: stage cur ready; prefetch ch+2 into (cur+2)%3 ----
    int cur = 0;
    for (int ch = 0; ch < NCH; ch++) {
        bool pre = (ch + 2) < NCH;
        int nxt = cur + 2; if (nxt >= NSTAGE) nxt -= NSTAGE;
        float4 v[2];
        if (pre) { ldA(ch + 2, v); ldB(ch + 2, nxt); }

        const unsigned* As = (const unsigned*)(dsm + cur * STAGE);
        const uint2*    Bf = (const uint2*)(dsm + cur * STAGE + A_PLANE);

        #pragma unroll
        for (int s = 0; s < 2; s++) {
            unsigned af[2][4];
            #pragma unroll
            for (int mt = 0; mt < 2; mt++) {
                int r0 = (wM * 32 + mt * 16 + g) * A_STRIDE_W + s * 8 + t4;
                int r8 = r0 + 8 * A_STRIDE_W;
                af[mt][0] = As[r0];     af[mt][1] = As[r8];
                af[mt][2] = As[r0 + 4]; af[mt][3] = As[r8 + 4];
            }
            #pragma unroll
            for (int nt = 0; nt < 4; nt++) {
                uint2 bf = Bf[(s * 16 + wN * 4 + nt) * 32 + lane];
                #pragma unroll
                for (int mt = 0; mt < 2; mt++)
                    mma_f16(acc[mt][nt], af[mt], bf.x, bf.y);
            }
        }

        if (pre) {
            stA(nxt, v);
            asm volatile("cp.async.wait_group 1;\n");
        } else {
            asm volatile("cp.async.wait_group 0;\n");
        }
        __syncthreads();
        cur = cur + 1 == NSTAGE ? 0 : cur + 1;
    }

    // ---- e[t] = bv + sum_a Wv[a]*tanh(acc + qq[a]) ----
    #pragma unroll
    for (int mt = 0; mt < 2; mt++) {
        #pragma unroll
        for (int half = 0; half < 2; half++) {
            int rloc = wM * 32 + mt * 16 + g + 8 * half;
            float p = 0.f;
            #pragma unroll
            for (int nt = 0; nt < 4; nt++) {
                int c0 = wN * 32 + nt * 8 + 2 * t4;
                float x0 = acc[mt][nt][2 * half + 0] + s_qq[c0];
                float x1 = acc[mt][nt][2 * half + 1] + s_qq[c0 + 1];
                float e0 = __expf(2.f * x0), e1 = __expf(2.f * x1);
                p += s_wv[c0]     * (1.f - __fdividef(2.f, e0 + 1.f));
                p += s_wv[c0 + 1] * (1.f - __fdividef(2.f, e1 + 1.f));
            }
            p += __shfl_xor_sync(0xffffffffu, p, 1);
            p += __shfl_xor_sync(0xffffffffu, p, 2);
            if (t4 == 0) atomicAdd(&s_esum[rloc], p);
        }
    }
    __syncthreads();

    // ---- flash partials: m_l, p_t, s_l, partial ctx ----
    if (tid < 32) {
        float m = fmaxf(s_esum[tid], s_esum[tid + 32]);
        #pragma unroll
        for (int o = 16; o; o >>= 1) m = fmaxf(m, __shfl_xor_sync(0xffffffffu, m, o));
        if (tid == 0) s_ml = m;
    }
    if (tid < TM) g_e[b][t0 + tid] = s_esum[tid] + bv0;
    __syncthreads();
    if (tid < TM) sp[tid] = __expf(s_esum[tid] - s_ml);
    __syncthreads();
    if (tid < 32) {
        float ssum = sp[tid] + sp[tid + 32];
        #pragma unroll
        for (int o = 16; o; o >>= 1) ssum += __shfl_xor_sync(0xffffffffu, ssum, o);
        if (tid == 0) g_ms[b * NTILE + tx] = make_float2(s_ml, ssum);
    }
    // partial context: pctx[d] = sum_t sp[t] * mem[t][d]  (tile is L2-hot)
    {
        const float* mp = memB + tid;
        float c0 = 0.f, c1 = 0.f;
        #pragma unroll 8
        for (int t = 0; t < TM; t++) {
            float wt = sp[t];
            c0 += wt * mp[(size_t)t * DE];
            c1 += wt * mp[(size_t)t * DE + 256];
        }
        g_pctx[((size_t)b * NTILE + tx) * DE + tid]       = c0;
        g_pctx[((size_t)b * NTILE + tx) * DE + tid + 256] = c1;
    }
}

// ---------------- K4: blocks 0..63 softmax -> out_w; 64..127 combine ctx -----
__global__ __launch_bounds__(512) void k_fin(float* __restrict__ out_w,
                                             float* __restrict__ out_ctx) {
    __shared__ float red[512];
    int tid = threadIdx.x;
    if (blockIdx.x < B) {
        int b = blockIdx.x;
        float v[4];
        float m = -1e30f;
        #pragma unroll
        for (int j = 0; j < 4; j++) { v[j] = g_e[b][tid + 512 * j]; m = fmaxf(m, v[j]); }
        red[tid] = m; __syncthreads();
        for (int s = 256; s; s >>= 1) { if (tid < s) red[tid] = fmaxf(red[tid], red[tid + s]); __syncthreads(); }
        m = red[0]; __syncthreads();
        float sum = 0.f;
        #pragma unroll
        for (int j = 0; j < 4; j++) { v[j] = expf(v[j] - m); sum += v[j]; }
        red[tid] = sum; __syncthreads();
        for (int s = 256; s; s >>= 1) { if (tid < s) red[tid] += red[tid + s]; __syncthreads(); }
        float inv = 1.f / red[0];
        #pragma unroll
        for (int j = 0; j < 4; j++) out_w[(size_t)b * T + tid + 512 * j] = v[j] * inv;
    } else {
        int b = blockIdx.x - B;
        __shared__ float sm[NTILE], ss[NTILE];
        if (tid < NTILE) {
            float2 v = g_ms[b * NTILE + tid];
            sm[tid] = v.x; ss[tid] = v.y;
        }
        __syncthreads();
        float mg = -1e30f;
        #pragma unroll
        for (int l = 0; l < NTILE; l++) mg = fmaxf(mg, sm[l]);
        float Sg = 0.f;
        float sc[NTILE];
        #pragma unroll
        for (int l = 0; l < NTILE; l++) { sc[l] = expf(sm[l] - mg); Sg += ss[l] * sc[l]; }
        float invS = 1.f / Sg;
        float acc = 0.f;
        #pragma unroll
        for (int l = 0; l < NTILE; l++)
            acc += sc[l] * g_pctx[((size_t)b * NTILE + l) * DE + tid];
        out_ctx[(size_t)b * DE + tid] = acc * invS;
    }
}

// ---------------- launch ------------------------------------------------------
extern "C" void kernel_launch(void* const* d_in, const int* in_sizes, int n_in,
                              void* d_out, int out_size) {
    const float* query  = (const float*)d_in[0];
    const float* memory = (const float*)d_in[1];
    const float* aw     = (const float*)d_in[2];
    const float* Wq     = (const float*)d_in[3];
    const float* bq     = (const float*)d_in[4];
    const float* Wm     = (const float*)d_in[5];
    const float* bm     = (const float*)d_in[6];
    const float* Wconv  = (const float*)d_in[7];
    const float* Wloc   = (const float*)d_in[8];
    const float* Wv     = (const float*)d_in[9];
    const float* bv     = (const float*)d_in[10];

    float* out_ctx = (float*)d_out;            // [B][DE]
    float* out_w   = (float*)d_out + B * DE;   // [B][T]

    k_qq   <<<dim3(B, 4), 128>>>(query, Wq, bq, bm);
    k_prepB<<<(NCH * 2 * 16 * 32 + 255) / 256, 256>>>(Wm, Wloc);
    k_conv <<<dim3(B, T / 128), 128>>>(aw, Wconv);
    k_main <<<dim3(NTILE, B), 256, DSM_BYTES>>>(memory, Wv, bv);
    k_fin  <<<2 * B, 512>>>(out_w, out_ctx);
}